// round 9
// baseline (speedup 1.0000x reference)
#include <cuda_runtime.h>
#include <cstdint>

#define BATCH 32
#define CIN   256
#define HW    3136          // 56*56
#define HWQ   784           // HW/4
#define CR    8
#define NPIX  (BATCH*HW)    // 100352
#define COUT  44            // 8 + 36

#define WCH   32            // channels per warp (8 warps = 256 ch)
#define QPB   32            // quads per block (= lanes), 128 px/block
#define PSTR  17            // padded partial row stride (u64)

// z buffer, pixel-major: [b][p][c], 32B per pixel record
__device__ float g_z[NPIX*CR];

typedef unsigned long long u64;

__device__ __forceinline__ u64 fma2(u64 a, u64 b, u64 c) {
    u64 d;
    asm("fma.rn.f32x2 %0, %1, %2, %3;" : "=l"(d) : "l"(a), "l"(b), "l"(c));
    return d;
}
__device__ __forceinline__ u64 add2(u64 a, u64 b) {
    u64 d;
    asm("add.rn.f32x2 %0, %1, %2;" : "=l"(d) : "l"(a), "l"(b));
    return d;
}
__device__ __forceinline__ u64 pack2(float lo, float hi) {
    u64 r;
    asm("mov.b64 %0, {%1, %2};" : "=l"(r) : "f"(lo), "f"(hi));
    return r;
}
__device__ __forceinline__ float2 unpack2(u64 v) {
    float2 r;
    asm("mov.b64 {%0, %1}, %2;" : "=f"(r.x), "=f"(r.y) : "l"(v));
    return r;
}

// ============================================================
// 1x1 conv + BN(folded) + ReLU.
// 256 thr = 8 warps; warp w owns 32 channels, lane owns 1 quad (4px).
// Registers-only 2-stage LDG.128 pipeline. grid = NPIX/128 = 784.
// smem union: weights (16KB) then partials (34.8KB).
// ============================================================
__global__ void __launch_bounds__(256) conv1x1_k(const float* __restrict__ x,
                                                 const float* __restrict__ wr,
                                                 const float* __restrict__ gamma,
                                                 const float* __restrict__ beta,
                                                 const float* __restrict__ mean,
                                                 const float* __restrict__ var) {
    __shared__ __align__(16) u64 su[8*QPB*PSTR];   // 34.8 KB union
    __shared__ float sinv[CR], sbias[CR];

    u64* sw = su;                        // weights live in first 2048 u64

    int tid  = threadIdx.x;
    int w    = tid >> 5;
    int lane = tid & 31;

    if (tid < CR) {
        int c = tid;
        float inv = gamma[c] * rsqrtf(var[c] + 1e-5f);
        sinv[c]  = inv;
        sbias[c] = beta[c] - mean[c] * inv;
    }
    __syncthreads();
    #pragma unroll
    for (int i = tid; i < CIN*CR; i += 256) {
        int ci = i >> 3;
        int c  = i & 7;
        float wgt = wr[c*CIN + ci] * sinv[c];
        sw[i] = pack2(wgt, wgt);
    }
    __syncthreads();

    int qq = blockIdx.x * QPB + lane;    // global quad (may straddle images)
    int b  = qq / HWQ;
    int qi = qq - b*HWQ;

    const ulonglong2* xp = reinterpret_cast<const ulonglong2*>(x)
                         + (size_t)(b*CIN + w*WCH)*HWQ + qi;

    u64 aL[CR], aH[CR];
    #pragma unroll
    for (int c = 0; c < CR; c++) { aL[c] = 0ull; aH[c] = 0ull; }

    ulonglong2 xa[4], xb[4];
    #pragma unroll
    for (int u = 0; u < 4; u++) xa[u] = xp[(size_t)u*HWQ];

    #pragma unroll 1
    for (int ci = 0; ci < WCH; ci += 8) {
        #pragma unroll
        for (int u = 0; u < 4; u++) xb[u] = xp[(size_t)(ci+4+u)*HWQ];
        #pragma unroll
        for (int u = 0; u < 4; u++) {
            const ulonglong2* wrow =
                reinterpret_cast<const ulonglong2*>(&sw[(w*WCH + ci + u)*CR]);
            ulonglong2 w01 = wrow[0], w23 = wrow[1], w45 = wrow[2], w67 = wrow[3];
            ulonglong2 xv = xa[u];
            aL[0]=fma2(w01.x,xv.x,aL[0]); aH[0]=fma2(w01.x,xv.y,aH[0]);
            aL[1]=fma2(w01.y,xv.x,aL[1]); aH[1]=fma2(w01.y,xv.y,aH[1]);
            aL[2]=fma2(w23.x,xv.x,aL[2]); aH[2]=fma2(w23.x,xv.y,aH[2]);
            aL[3]=fma2(w23.y,xv.x,aL[3]); aH[3]=fma2(w23.y,xv.y,aH[3]);
            aL[4]=fma2(w45.x,xv.x,aL[4]); aH[4]=fma2(w45.x,xv.y,aH[4]);
            aL[5]=fma2(w45.y,xv.x,aL[5]); aH[5]=fma2(w45.y,xv.y,aH[5]);
            aL[6]=fma2(w67.x,xv.x,aL[6]); aH[6]=fma2(w67.x,xv.y,aH[6]);
            aL[7]=fma2(w67.y,xv.x,aL[7]); aH[7]=fma2(w67.y,xv.y,aH[7]);
        }
        if (ci + 8 < WCH) {
            #pragma unroll
            for (int u = 0; u < 4; u++) xa[u] = xp[(size_t)(ci+8+u)*HWQ];
        }
        #pragma unroll
        for (int u = 0; u < 4; u++) {
            const ulonglong2* wrow =
                reinterpret_cast<const ulonglong2*>(&sw[(w*WCH + ci + 4 + u)*CR]);
            ulonglong2 w01 = wrow[0], w23 = wrow[1], w45 = wrow[2], w67 = wrow[3];
            ulonglong2 xv = xb[u];
            aL[0]=fma2(w01.x,xv.x,aL[0]); aH[0]=fma2(w01.x,xv.y,aH[0]);
            aL[1]=fma2(w01.y,xv.x,aL[1]); aH[1]=fma2(w01.y,xv.y,aH[1]);
            aL[2]=fma2(w23.x,xv.x,aL[2]); aH[2]=fma2(w23.x,xv.y,aH[2]);
            aL[3]=fma2(w23.y,xv.x,aL[3]); aH[3]=fma2(w23.y,xv.y,aH[3]);
            aL[4]=fma2(w45.x,xv.x,aL[4]); aH[4]=fma2(w45.x,xv.y,aH[4]);
            aL[5]=fma2(w45.y,xv.x,aL[5]); aH[5]=fma2(w45.y,xv.y,aH[5]);
            aL[6]=fma2(w67.x,xv.x,aL[6]); aH[6]=fma2(w67.x,xv.y,aH[6]);
            aL[7]=fma2(w67.y,xv.x,aL[7]); aH[7]=fma2(w67.y,xv.y,aH[7]);
        }
    }

    __syncthreads();                     // everyone done reading weights

    // partials: row per (warp, lane); layout [p2*8 + c]
    {
        u64* row = &su[(size_t)(w*QPB + lane)*PSTR];
        #pragma unroll
        for (int c = 0; c < CR; c++) { row[c] = aL[c]; row[CR + c] = aH[c]; }
    }
    __syncthreads();

    // reduce: thread -> (quad q, pair p2, channel-pair cc)
    {
        int q  = tid >> 3;
        int g  = tid & 7;
        int p2 = g >> 2;
        int cc = g & 3;
        u64 s0 = 0ull, s1 = 0ull;
        #pragma unroll
        for (int k = 0; k < 8; k++) {
            const u64* row = &su[(size_t)(k*QPB + q)*PSTR + p2*CR + 2*cc];
            s0 = add2(s0, row[0]);
            s1 = add2(s1, row[1]);
        }
        float2 v0 = unpack2(s0);         // ch 2cc : (pxA, pxB)
        float2 v1 = unpack2(s1);         // ch 2cc+1
        float b0 = sbias[2*cc], b1 = sbias[2*cc+1];
        float a0 = fmaxf(v0.x + b0, 0.f), a1 = fmaxf(v1.x + b1, 0.f);
        float c0 = fmaxf(v0.y + b0, 0.f), c1 = fmaxf(v1.y + b1, 0.f);
        int qq2 = blockIdx.x*QPB + q;
        int b2  = qq2 / HWQ;
        int qi2 = qq2 - b2*HWQ;
        int px0 = qi2*4 + p2*2;
        float2* z0 = reinterpret_cast<float2*>(g_z + ((size_t)b2*HW + px0)*CR + 2*cc);
        float2* z1 = reinterpret_cast<float2*>(g_z + ((size_t)b2*HW + px0 + 1)*CR + 2*cc);
        *z0 = make_float2(a0, a1);
        *z1 = make_float2(c0, c1);
    }
}

// ============================================================
// Depthwise 3x3 (scale folded) + L2-norms + pairwise products.
// 2 adjacent px/thread; halo-padded planes; all stores STG.64.
// grid = 32 images x 14 bands = 448 blocks of 112 threads.
// ============================================================
#define TW 58
__global__ void __launch_bounds__(112) twist_k(float* __restrict__ out,
                                               const float* __restrict__ wdw,
                                               const float* __restrict__ scale) {
    __shared__ float4 sA[6*TW];
    __shared__ float4 sC[6*TW];
    __shared__ float  swd[CR*9];

    int tid = threadIdx.x;
    if (tid < CR*9) swd[tid] = wdw[tid] * scale[tid/9];

    int b    = blockIdx.x / 14;
    int band = blockIdx.x - b*14;
    int y0   = band * 4;

    const float4* zb = reinterpret_cast<const float4*>(g_z) + (size_t)b*HW*2;

    for (int f = tid; f < 6*TW; f += 112) {
        int r  = f / TW;
        int c  = f - r*TW;
        int gy = y0 + r - 1;
        int gx = c - 1;
        float4 va = make_float4(0.f,0.f,0.f,0.f);
        float4 vc = va;
        if ((unsigned)gy < 56u && (unsigned)gx < 56u) {
            size_t q = (size_t)(gy*56 + gx)*2;
            va = __ldg(&zb[q]);
            vc = __ldg(&zb[q+1]);
        }
        sA[f] = va;
        sC[f] = vc;
    }
    __syncthreads();

    int row = tid / 28;                  // 0..3
    int cp  = tid - row*28;              // 0..27
    int col = cp*2;                      // even pixel 0..54
    int s0  = (row+1)*TW + (col+1);      // smem center of px0

    float tA[CR], tB[CR];
    #pragma unroll
    for (int c = 0; c < CR; c++) { tA[c] = 0.f; tB[c] = 0.f; }

    float zA[CR], zB[CR];
    {
        float4 a = sA[s0],   c4 = sC[s0];
        zA[0]=a.x; zA[1]=a.y; zA[2]=a.z; zA[3]=a.w;
        zA[4]=c4.x; zA[5]=c4.y; zA[6]=c4.z; zA[7]=c4.w;
        float4 a1 = sA[s0+1], c1 = sC[s0+1];
        zB[0]=a1.x; zB[1]=a1.y; zB[2]=a1.z; zB[3]=a1.w;
        zB[4]=c1.x; zB[5]=c1.y; zB[6]=c1.z; zB[7]=c1.w;
    }

    #pragma unroll
    for (int dy = -1; dy <= 1; dy++) {
        #pragma unroll
        for (int dc = -1; dc <= 2; dc++) {
            int si = s0 + dy*TW + dc;
            float4 a  = sA[si];
            float4 c4 = sC[si];
            float v[CR] = {a.x,a.y,a.z,a.w,c4.x,c4.y,c4.z,c4.w};
            if (dc <= 1) {               // tap for px0, kx = dc+1
                int k = (dy+1)*3 + (dc+1);
                #pragma unroll
                for (int c = 0; c < CR; c++) tA[c] = fmaf(v[c], swd[c*9+k], tA[c]);
            }
            if (dc >= 0) {               // tap for px1, kx = dc
                int k = (dy+1)*3 + dc;
                #pragma unroll
                for (int c = 0; c < CR; c++) tB[c] = fmaf(v[c], swd[c*9+k], tB[c]);
            }
        }
    }

    float szA=0.f, stA=0.f, szB=0.f, stB=0.f;
    #pragma unroll
    for (int c = 0; c < CR; c++) {
        szA = fmaf(zA[c], zA[c], szA); stA = fmaf(tA[c], tA[c], stA);
        szB = fmaf(zB[c], zB[c], szB); stB = fmaf(tB[c], tB[c], stB);
    }
    float izA = 1.0f / fmaxf(sqrtf(szA), 1e-6f);
    float itA = 1.0f / fmaxf(sqrtf(stA), 1e-6f);
    float izB = 1.0f / fmaxf(sqrtf(szB), 1e-6f);
    float itB = 1.0f / fmaxf(sqrtf(stB), 1e-6f);

    #pragma unroll
    for (int c = 0; c < CR; c++) {
        zA[c] *= izA; tA[c] *= itA;
        zB[c] *= izB; tB[c] *= itB;
    }

    int p = (y0 + row)*56 + col;
    float2* ob = reinterpret_cast<float2*>(out + (size_t)b*COUT*HW + p);
    const int STR = HW/2;                // plane stride in float2
    #pragma unroll
    for (int c = 0; c < CR; c++) ob[(size_t)c*STR] = make_float2(zA[c], zB[c]);

    int k = 8;
    #pragma unroll
    for (int i = 0; i < CR; i++) {
        #pragma unroll
        for (int j = i; j < CR; j++) {
            ob[(size_t)k*STR] = make_float2(zA[i]*tA[j], zB[i]*tB[j]);
            k++;
        }
    }
}

// ============================================================
extern "C" void kernel_launch(void* const* d_in, const int* in_sizes, int n_in,
                              void* d_out, int out_size) {
    const float* x     = (const float*)d_in[0];
    const float* wr    = (const float*)d_in[1];
    const float* gamma = (const float*)d_in[2];
    const float* beta  = (const float*)d_in[3];
    const float* mean  = (const float*)d_in[4];
    const float* var   = (const float*)d_in[5];
    const float* wdw   = (const float*)d_in[6];
    const float* scale = (const float*)d_in[7];
    float* out = (float*)d_out;

    conv1x1_k<<<NPIX/128, 256>>>(x, wr, gamma, beta, mean, var);
    twist_k<<<BATCH*14, 112>>>(out, wdw, scale);
}